// round 8
// baseline (speedup 1.0000x reference)
#include <cuda_runtime.h>
#include <math.h>

#define B_SZ 512
#define T_SZ 256
#define F_SZ 1024
#define SPLITK 4
#define KSLICE (F_SZ / SPLITK)   // 256
#define BK 32
#define NTILES (KSLICE / BK)     // 8
#define TSPLIT 4
#define TCH (T_SZ / TSPLIT)      // 64
#define NIT (TCH / 8)            // 8

// Scratch (allocation-free rule: __device__ globals)
__device__ float  g_q[B_SZ * F_SZ];
__device__ float  g_ctxf[B_SZ * F_SZ];
__device__ float  g_part[SPLITK * B_SZ * F_SZ];
__device__ float  g_pacc[TSPLIT * B_SZ * F_SZ];
__device__ float2 g_pmz[TSPLIT * B_SZ];

typedef unsigned long long u64;

__device__ __forceinline__ void ffma2(u64& d, u64 a, u64 b) {
    asm("fma.rn.f32x2 %0, %1, %2, %0;" : "+l"(d) : "l"(a), "l"(b));
}
__device__ __forceinline__ float2 u64_f2(u64 v) {
    float2 f;
    f.x = __uint_as_float((unsigned int)v);
    f.y = __uint_as_float((unsigned int)(v >> 32));
    return f;
}

// ---------------------------------------------------------------------------
// Split-K SGEMM, M=512, N=1024, K=1024. 64x64 tile, BK=32, 256 threads,
// 4x4 micro-tile via fp32x2 FMA.
// A is stored DUPLICATED in SMEM (As[k][2r]=As[k][2r+1]=A[r][k]) so the
// FFMA2 "scalar" operand is loaded pre-paired -> no MOV packs in the loop.
// occ 3 (85 regs, no spills). Inner loop: 3 LDS.128 + 8 FFMA2 per k-step.
// ---------------------------------------------------------------------------
template <bool B_IS_NT>
__global__ __launch_bounds__(256, 3) void sgemm_splitk(const float* __restrict__ A,
                                                       const float* __restrict__ Bm,
                                                       float* __restrict__ Cpart)
{
    __shared__ float As[2][BK][128];   // duplicated A: 32 KB
    __shared__ float Bs[2][BK][64];    // 16 KB  (total 48 KB)

    const int bm = blockIdx.y * 64;
    const int bn = blockIdx.x * 64;
    const int s  = blockIdx.z;
    const int k0 = s * KSLICE;
    const int tid = threadIdx.x;
    const int lrow = tid >> 2;            // 0..63   (row-major loads)
    const int lk   = (tid & 3) * 4;       // 0,4,8,12
    const int krow = tid >> 3;            // 0..31   (NN B loads)
    const int nq   = (tid & 7) * 4;       // 0..28
    const int ty = tid >> 4;              // 0..15
    const int tx = tid & 15;              // 0..15

    const float* Ap = A + (size_t)(bm + lrow) * F_SZ + k0 + lk;
    const float* Bp = B_IS_NT ? Bm + (size_t)(bn + lrow) * F_SZ + k0 + lk
                              : Bm + (size_t)(k0 + krow) * F_SZ + bn + nq;

    float4 ra0 = *(const float4*)Ap;
    float4 ra1 = *(const float4*)(Ap + 16);
    float4 rb0, rb1;
    if (B_IS_NT) { rb0 = *(const float4*)Bp; rb1 = *(const float4*)(Bp + 16); }
    else         { rb0 = *(const float4*)Bp; rb1 = *(const float4*)(Bp + 32); }

    u64 acc[4][2];
    #pragma unroll
    for (int i = 0; i < 4; i++) { acc[i][0] = 0ull; acc[i][1] = 0ull; }

    // stage tile 0 (A duplicated)
    #pragma unroll
    for (int j = 0; j < 4; j++) {
        As[0][lk + j][2 * lrow]          = (&ra0.x)[j];
        As[0][lk + j][2 * lrow + 1]      = (&ra0.x)[j];
        As[0][lk + 16 + j][2 * lrow]     = (&ra1.x)[j];
        As[0][lk + 16 + j][2 * lrow + 1] = (&ra1.x)[j];
    }
    if (B_IS_NT) {
        #pragma unroll
        for (int j = 0; j < 4; j++) {
            Bs[0][lk + j][lrow]      = (&rb0.x)[j];
            Bs[0][lk + 16 + j][lrow] = (&rb1.x)[j];
        }
    } else {
        *(float4*)&Bs[0][krow][nq]      = rb0;
        *(float4*)&Bs[0][krow][nq + 32] = rb1;
    }
    __syncthreads();

    int buf = 0;
    for (int kt = 0; kt < NTILES; kt++) {
        if (kt + 1 < NTILES) {                       // prefetch next tile
            ra0 = *(const float4*)(Ap + (kt + 1) * BK);
            ra1 = *(const float4*)(Ap + (kt + 1) * BK + 16);
            if (B_IS_NT) {
                rb0 = *(const float4*)(Bp + (kt + 1) * BK);
                rb1 = *(const float4*)(Bp + (kt + 1) * BK + 16);
            } else {
                rb0 = *(const float4*)(Bp + (size_t)(kt + 1) * BK * F_SZ);
                rb1 = *(const float4*)(Bp + (size_t)(kt + 1) * BK * F_SZ + 32);
            }
        }

        #pragma unroll
        for (int kk = 0; kk < BK; kk++) {
            ulonglong2 av01 = *(const ulonglong2*)&As[buf][kk][ty * 8];     // (a0,a0),(a1,a1)
            ulonglong2 av23 = *(const ulonglong2*)&As[buf][kk][ty * 8 + 4]; // (a2,a2),(a3,a3)
            ulonglong2 bv   = *(const ulonglong2*)&Bs[buf][kk][tx * 4];
            ffma2(acc[0][0], av01.x, bv.x); ffma2(acc[0][1], av01.x, bv.y);
            ffma2(acc[1][0], av01.y, bv.x); ffma2(acc[1][1], av01.y, bv.y);
            ffma2(acc[2][0], av23.x, bv.x); ffma2(acc[2][1], av23.x, bv.y);
            ffma2(acc[3][0], av23.y, bv.x); ffma2(acc[3][1], av23.y, bv.y);
        }

        if (kt + 1 < NTILES) {
            int nb = buf ^ 1;
            #pragma unroll
            for (int j = 0; j < 4; j++) {
                As[nb][lk + j][2 * lrow]          = (&ra0.x)[j];
                As[nb][lk + j][2 * lrow + 1]      = (&ra0.x)[j];
                As[nb][lk + 16 + j][2 * lrow]     = (&ra1.x)[j];
                As[nb][lk + 16 + j][2 * lrow + 1] = (&ra1.x)[j];
            }
            if (B_IS_NT) {
                #pragma unroll
                for (int j = 0; j < 4; j++) {
                    Bs[nb][lk + j][lrow]      = (&rb0.x)[j];
                    Bs[nb][lk + 16 + j][lrow] = (&rb1.x)[j];
                }
            } else {
                *(float4*)&Bs[nb][krow][nq]      = rb0;
                *(float4*)&Bs[nb][krow][nq + 32] = rb1;
            }
            __syncthreads();
            buf = nb;
        }
    }

    float* Cp = Cpart + (size_t)s * (B_SZ * F_SZ)
                      + (size_t)(bm + ty * 4) * F_SZ + bn + tx * 4;
    #pragma unroll
    for (int i = 0; i < 4; i++) {
        float2 p0 = u64_f2(acc[i][0]);
        float2 p1 = u64_f2(acc[i][1]);
        float4 o = make_float4(p0.x, p0.y, p1.x, p1.y);
        *(float4*)(Cp + (size_t)i * F_SZ) = o;
    }
}

// ---------------------------------------------------------------------------
// Reduce SPLITK partials (+ bias). 4 float4 per thread -> MLP 16.
// grid = B*F/4/256/4 = 128 blocks.
// ---------------------------------------------------------------------------
template <bool HAS_BIAS>
__global__ __launch_bounds__(256) void reduce_k(const float* __restrict__ part,
                                                const float* __restrict__ bias,
                                                float* __restrict__ out)
{
    const int base = blockIdx.x * 1024 + threadIdx.x;
    const int Q = B_SZ * F_SZ / 4;
    const float4* p = (const float4*)part;

    float4 a[4], b[4], c[4], d[4];
    #pragma unroll
    for (int u = 0; u < 4; u++) {
        int idx = base + u * 256;
        a[u] = p[idx];
        b[u] = p[idx + Q];
        c[u] = p[idx + 2 * Q];
        d[u] = p[idx + 3 * Q];
    }
    #pragma unroll
    for (int u = 0; u < 4; u++) {
        int idx = base + u * 256;
        float4 o;
        o.x = (a[u].x + b[u].x) + (c[u].x + d[u].x);
        o.y = (a[u].y + b[u].y) + (c[u].y + d[u].y);
        o.z = (a[u].z + b[u].z) + (c[u].z + d[u].z);
        o.w = (a[u].w + b[u].w) + (c[u].w + d[u].w);
        if (HAS_BIAS) {
            float4 bb = ((const float4*)bias)[idx & (F_SZ / 4 - 1)];
            o.x += bb.x; o.y += bb.y; o.z += bb.z; o.w += bb.w;
        }
        ((float4*)out)[idx] = o;
    }
}

// ---------------------------------------------------------------------------
// Attention partial, fully register-resident: grid (B, TSPLIT).
// ---------------------------------------------------------------------------
__global__ __launch_bounds__(256, 2) void attn_part(const float* __restrict__ x,
                                                    const float* __restrict__ qkpart,
                                                    float* __restrict__ pacc,
                                                    float2* __restrict__ pmz)
{
    const int b = blockIdx.x;
    const int h = blockIdx.y;
    const int tid = threadIdx.x;
    const int w = tid >> 5;
    const int l = tid & 31;

    __shared__ float red[8][256];      // 8 KB
    __shared__ float s_tile[8];

    // qk[b, 4*tid .. 4*tid+3] = sum of 4 split-K partials -> registers
    float4 qk;
    {
        const int Q = B_SZ * F_SZ / 4;
        const int idx = b * 256 + tid;
        const float4* p = (const float4*)qkpart;
        float4 a = p[idx], bb = p[idx + Q], c = p[idx + 2 * Q], d = p[idx + 3 * Q];
        qk = make_float4((a.x + bb.x) + (c.x + d.x),
                         (a.y + bb.y) + (c.y + d.y),
                         (a.z + bb.z) + (c.z + d.z),
                         (a.w + bb.w) + (c.w + d.w));
    }

    const float4* x4 = (const float4*)(x + (size_t)b * T_SZ * F_SZ
                                         + (size_t)h * TCH * F_SZ);

    float4 cur[8], nxt[8];
    #pragma unroll
    for (int i = 0; i < 8; i++) cur[i] = x4[(size_t)i * 256 + tid];

    float m = -INFINITY, Z = 0.0f;
    float4 acc = make_float4(0.f, 0.f, 0.f, 0.f);

    #pragma unroll
    for (int it = 0; it < NIT; it++) {
        if (it + 1 < NIT) {            // next tile LDGs in flight over scores
            #pragma unroll
            for (int i = 0; i < 8; i++)
                nxt[i] = x4[(size_t)((it + 1) * 8 + i) * 256 + tid];
        }

        // partial scores from registers -> red
        #pragma unroll
        for (int i = 0; i < 8; i++) {
            float4 xv = cur[i];
            red[i][tid] = xv.x * qk.x + xv.y * qk.y + xv.z * qk.z + xv.w * qk.w;
        }
        __syncthreads();

        // warp w reduces row w (256 partials)
        {
            float s = 0.f;
            #pragma unroll
            for (int j = 0; j < 8; j++) s += red[w][l + 32 * j];
            #pragma unroll
            for (int off = 16; off; off >>= 1)
                s += __shfl_down_sync(0xffffffffu, s, off);
            if (l == 0) s_tile[w] = s;
        }
        __syncthreads();

        // online softmax + register accumulation
        float tm = s_tile[0];
        #pragma unroll
        for (int t = 1; t < 8; t++) tm = fmaxf(tm, s_tile[t]);
        float m_new = fmaxf(m, tm);
        float scale = __expf(m - m_new);
        Z *= scale;
        acc.x *= scale; acc.y *= scale; acc.z *= scale; acc.w *= scale;

        #pragma unroll
        for (int t = 0; t < 8; t++) {
            float wt = __expf(s_tile[t] - m_new);
            Z += wt;
            float4 xv = cur[t];
            acc.x += wt * xv.x; acc.y += wt * xv.y;
            acc.z += wt * xv.z; acc.w += wt * xv.w;
        }
        m = m_new;

        if (it + 1 < NIT) {
            #pragma unroll
            for (int i = 0; i < 8; i++) cur[i] = nxt[i];
        }
    }

    ((float4*)pacc)[(size_t)(b * TSPLIT + h) * 256 + tid] = acc;
    if (tid == 0) pmz[b * TSPLIT + h] = make_float2(m, Z);
}

// ---------------------------------------------------------------------------
// Combine the TSPLIT T-chunks (flash merge), normalize -> ctxf.
// ---------------------------------------------------------------------------
__global__ __launch_bounds__(256) void attn_combine(const float* __restrict__ pacc,
                                                    const float2* __restrict__ pmz,
                                                    float* __restrict__ ctxf)
{
    const int b = blockIdx.x;
    const int tid = threadIdx.x;

    float2 mz[TSPLIT];
    #pragma unroll
    for (int i = 0; i < TSPLIT; i++) mz[i] = pmz[TSPLIT * b + i];
    float m = mz[0].x;
    #pragma unroll
    for (int i = 1; i < TSPLIT; i++) m = fmaxf(m, mz[i].x);

    float sc[TSPLIT];
    float Z = 0.f;
    #pragma unroll
    for (int i = 0; i < TSPLIT; i++) { sc[i] = __expf(mz[i].x - m); Z += mz[i].y * sc[i]; }
    float inv = 1.0f / Z;

    float4 o = make_float4(0.f, 0.f, 0.f, 0.f);
    #pragma unroll
    for (int i = 0; i < TSPLIT; i++) {
        float4 a = ((const float4*)pacc)[(size_t)(TSPLIT * b + i) * 256 + tid];
        o.x += a.x * sc[i]; o.y += a.y * sc[i];
        o.z += a.z * sc[i]; o.w += a.w * sc[i];
    }
    o.x *= inv; o.y *= inv; o.z *= inv; o.w *= inv;
    ((float4*)(ctxf + (size_t)b * F_SZ))[tid] = o;
}

// ---------------------------------------------------------------------------
extern "C" void kernel_launch(void* const* d_in, const int* in_sizes, int n_in,
                              void* d_out, int out_size)
{
    const float* z  = (const float*)d_in[0];   // [B,F]
    const float* x  = (const float*)d_in[1];   // [B,T,F]
    const float* Wq = (const float*)d_in[2];   // [D,F]
    const float* Wk = (const float*)d_in[3];   // [D,F]
    const float* Wv = (const float*)d_in[4];   // [D,F]
    const float* bq = (const float*)d_in[5];   // [D]
    // d_in[6] = bk: softmax-invariant (constant shift per row) -> dropped
    const float* bv = (const float*)d_in[7];   // [D]
    float* out = (float*)d_out;                // [B,D]

    float *q, *ctxf, *part, *pacc;
    float2* pmz;
    cudaGetSymbolAddress((void**)&q,    g_q);
    cudaGetSymbolAddress((void**)&ctxf, g_ctxf);
    cudaGetSymbolAddress((void**)&part, g_part);
    cudaGetSymbolAddress((void**)&pacc, g_pacc);
    cudaGetSymbolAddress((void**)&pmz,  g_pmz);

    dim3 ggrid(F_SZ / 64, B_SZ / 64, SPLITK);   // (16, 8, 4) = 512 CTAs
    const int rgrid = B_SZ * F_SZ / 4 / 1024;   // 128 blocks

    // 1. q = z @ Wq^T + bq
    sgemm_splitk<true><<<ggrid, 256>>>(z, Wq, part);
    reduce_k<true><<<rgrid, 256>>>(part, bq, q);
    // 2. qk = q @ Wk   (partials consumed directly by attn_part)
    sgemm_splitk<false><<<ggrid, 256>>>(q, Wk, part);
    // 3. fused scores + softmax + weighted-input accumulation, T split in 4
    attn_part<<<dim3(B_SZ, TSPLIT), 256>>>(x, part, pacc, pmz);
    attn_combine<<<B_SZ, 256>>>(pacc, pmz, ctxf);
    // 4. out = ctxf @ Wv^T + bv
    sgemm_splitk<true><<<ggrid, 256>>>(ctxf, Wv, part);
    reduce_k<true><<<rgrid, 256>>>(part, bv, out);
}

// round 10
// speedup vs baseline: 1.4060x; 1.4060x over previous
#include <cuda_runtime.h>
#include <cuda_bf16.h>
#include <math.h>
#include <stdint.h>

#define B_SZ 512
#define T_SZ 256
#define F_SZ 1024
#define KP   3072               // K' = 3*F (tri-concat bf16 split)
#define SPLITK 4
#define KSL  (KP / SPLITK)      // 768 per split slice
#define NSTAGE (KSL / 32)       // 24 stages of 32 bf16
#define SROW 40                 // smem row stride in bf16 (conflict-free)
#define TSPLIT 4
#define TCH (T_SZ / TSPLIT)     // 64
#define NIT (TCH / 8)           // 8

// Scratch (allocation-free rule: __device__ globals)
__device__ float  g_part[SPLITK * B_SZ * F_SZ];
__device__ float  g_pacc[TSPLIT * B_SZ * F_SZ];
__device__ float2 g_pmz[TSPLIT * B_SZ];
__device__ __nv_bfloat16 g_actA[B_SZ * KP];   // activation triple (z -> q -> ctxf)
__device__ __nv_bfloat16 g_WqB[F_SZ * KP];
__device__ __nv_bfloat16 g_WkB[F_SZ * KP];    // transposed Wk triple
__device__ __nv_bfloat16 g_WvB[F_SZ * KP];

// ===========================================================================
// bf16 split helpers
// ===========================================================================
__device__ __forceinline__ void split4(float4 v, uint2& hi, uint2& lo) {
    __nv_bfloat16 hx = __float2bfloat16_rn(v.x), hy = __float2bfloat16_rn(v.y);
    __nv_bfloat16 hz = __float2bfloat16_rn(v.z), hw = __float2bfloat16_rn(v.w);
    __nv_bfloat16 lx = __float2bfloat16_rn(v.x - __bfloat162float(hx));
    __nv_bfloat16 ly = __float2bfloat16_rn(v.y - __bfloat162float(hy));
    __nv_bfloat16 lz = __float2bfloat16_rn(v.z - __bfloat162float(hz));
    __nv_bfloat16 lw = __float2bfloat16_rn(v.w - __bfloat162float(hw));
    __nv_bfloat162 h0 = __nv_bfloat162(hx, hy), h1 = __nv_bfloat162(hz, hw);
    __nv_bfloat162 l0 = __nv_bfloat162(lx, ly), l1 = __nv_bfloat162(lz, lw);
    hi.x = *(unsigned*)&h0; hi.y = *(unsigned*)&h1;
    lo.x = *(unsigned*)&l0; lo.y = *(unsigned*)&l1;
}

// Weight conversion, no transpose, B-pattern [hi | hi | lo]. grid 1024 x 256.
__global__ __launch_bounds__(256) void conv_w_nt(const float* __restrict__ W,
                                                 __nv_bfloat16* __restrict__ out)
{
    int idx = blockIdx.x * 256 + threadIdx.x;     // float4 over 1024x256
    int row = idx >> 8, c = (idx & 255) * 4;
    float4 v = ((const float4*)W)[idx];
    uint2 hi, lo; split4(v, hi, lo);
    __nv_bfloat16* base = out + (size_t)row * KP + c;
    *(uint2*)(base)        = hi;
    *(uint2*)(base + 1024) = hi;
    *(uint2*)(base + 2048) = lo;
}

// Wk transpose + convert, B-pattern. grid (32,32), block (32,8).
__global__ void conv_w_t(const float* __restrict__ W, __nv_bfloat16* __restrict__ out)
{
    __shared__ float t[32][33];
    int f0 = blockIdx.x * 32, d0 = blockIdx.y * 32;
    int tx = threadIdx.x, ty = threadIdx.y;
    #pragma unroll
    for (int i = 0; i < 32; i += 8)
        t[ty + i][tx] = W[(size_t)(d0 + ty + i) * F_SZ + f0 + tx];   // t[dd][ff]
    __syncthreads();
    #pragma unroll
    for (int i = 0; i < 32; i += 8) {
        float v = t[tx][ty + i];                   // dd=tx, ff=ty+i
        __nv_bfloat16 hi = __float2bfloat16_rn(v);
        __nv_bfloat16 lo = __float2bfloat16_rn(v - __bfloat162float(hi));
        __nv_bfloat16* base = out + (size_t)(f0 + ty + i) * KP + d0 + tx;
        base[0]    = hi;
        base[1024] = hi;
        base[2048] = lo;
    }
}

// Activation conversion, A-pattern [hi | lo | hi]. grid 512 x 256.
__global__ __launch_bounds__(256) void conv_act(const float* __restrict__ X,
                                                __nv_bfloat16* __restrict__ out)
{
    int idx = blockIdx.x * 256 + threadIdx.x;     // float4 over 512x256
    int row = idx >> 8, c = (idx & 255) * 4;
    float4 v = ((const float4*)X)[idx];
    uint2 hi, lo; split4(v, hi, lo);
    __nv_bfloat16* base = out + (size_t)row * KP + c;
    *(uint2*)(base)        = hi;
    *(uint2*)(base + 1024) = lo;
    *(uint2*)(base + 2048) = hi;
}

// Reduce split-K partials + bias -> A-pattern bf16 triple. grid 512 x 256.
__global__ __launch_bounds__(256) void reduce_conv(const float* __restrict__ part,
                                                   const float* __restrict__ bias,
                                                   __nv_bfloat16* __restrict__ out)
{
    const int idx = blockIdx.x * 256 + threadIdx.x;
    const int Q = B_SZ * F_SZ / 4;
    const float4* p = (const float4*)part;
    float4 a = p[idx], b = p[idx + Q], c4 = p[idx + 2 * Q], d = p[idx + 3 * Q];
    float4 bb = ((const float4*)bias)[idx & 255];
    float4 v;
    v.x = (a.x + b.x) + (c4.x + d.x) + bb.x;
    v.y = (a.y + b.y) + (c4.y + d.y) + bb.y;
    v.z = (a.z + b.z) + (c4.z + d.z) + bb.z;
    v.w = (a.w + b.w) + (c4.w + d.w) + bb.w;
    int row = idx >> 8, c = (idx & 255) * 4;
    uint2 hi, lo; split4(v, hi, lo);
    __nv_bfloat16* base = out + (size_t)row * KP + c;
    *(uint2*)(base)        = hi;
    *(uint2*)(base + 1024) = lo;
    *(uint2*)(base + 2048) = hi;
}

// ===========================================================================
// bf16 HMMA GEMM via mma.sync.m16n8k16 (tensor pipe, sm_80+ PTX).
// CTA tile 128x128, 8 warps (2x4 -> 64x32 each), BK=32 stages, double-buffered
// SMEM (stride-40 rows, conflict-free fragment LDS), register prefetch.
// A':[512,KP], B':[1024,KP] K-major bf16. Grid (8, 4, SPLITK).
// ===========================================================================
__device__ __forceinline__ void mma16816(float* c, const uint32_t* a, const uint32_t* b) {
    asm volatile(
        "mma.sync.aligned.m16n8k16.row.col.f32.bf16.bf16.f32 "
        "{%0,%1,%2,%3}, {%4,%5,%6,%7}, {%8,%9}, {%0,%1,%2,%3};"
        : "+f"(c[0]), "+f"(c[1]), "+f"(c[2]), "+f"(c[3])
        : "r"(a[0]), "r"(a[1]), "r"(a[2]), "r"(a[3]), "r"(b[0]), "r"(b[1]));
}

__global__ __launch_bounds__(256) void mma_gemm(const __nv_bfloat16* __restrict__ Aq,
                                                const __nv_bfloat16* __restrict__ Bq,
                                                float* __restrict__ Cpart)
{
    __shared__ __align__(16) __nv_bfloat16 sA[2][128 * SROW];   // 10 KB x2
    __shared__ __align__(16) __nv_bfloat16 sB[2][128 * SROW];   // 10 KB x2

    const int bn = blockIdx.x * 128;
    const int bm = blockIdx.y * 128;
    const int s  = blockIdx.z;
    const int k0 = s * KSL;
    const int tid = threadIdx.x;
    const int wid = tid >> 5;
    const int l = tid & 31;
    const int wm = wid & 1;        // 0..1 -> 64 M-rows each
    const int wn = wid >> 1;       // 0..3 -> 32 N-cols each
    const int lq = l >> 2;         // lane/4
    const int lr = l & 3;          // lane%4

    // staging map: 512 uint4 per 128x32 tile, 2 per thread
    const int row0 = tid >> 2,           kc0 = (tid & 3) * 8;
    const int row1 = (tid + 256) >> 2,   kc1 = (tid & 3) * 8;   // rows 64..127

    const __nv_bfloat16* Ag0 = Aq + (size_t)(bm + row0) * KP + k0 + kc0;
    const __nv_bfloat16* Ag1 = Aq + (size_t)(bm + row1) * KP + k0 + kc1;
    const __nv_bfloat16* Bg0 = Bq + (size_t)(bn + row0) * KP + k0 + kc0;
    const __nv_bfloat16* Bg1 = Bq + (size_t)(bn + row1) * KP + k0 + kc1;

    const int sa0 = row0 * SROW + kc0, sa1 = row1 * SROW + kc1;

    float acc[4][4][4];
    #pragma unroll
    for (int i = 0; i < 4; i++)
        #pragma unroll
        for (int j = 0; j < 4; j++)
            #pragma unroll
            for (int r = 0; r < 4; r++) acc[i][j][r] = 0.f;

    // stage 0
    {
        uint4 a0 = *(const uint4*)Ag0, a1 = *(const uint4*)Ag1;
        uint4 b0 = *(const uint4*)Bg0, b1 = *(const uint4*)Bg1;
        *(uint4*)&sA[0][sa0] = a0; *(uint4*)&sA[0][sa1] = a1;
        *(uint4*)&sB[0][sa0] = b0; *(uint4*)&sB[0][sa1] = b1;
    }
    __syncthreads();

    int buf = 0;
    for (int st = 0; st < NSTAGE; st++) {
        uint4 pa0, pa1, pb0, pb1;
        if (st + 1 < NSTAGE) {                 // prefetch next stage to regs
            pa0 = *(const uint4*)(Ag0 + (st + 1) * 32);
            pa1 = *(const uint4*)(Ag1 + (st + 1) * 32);
            pb0 = *(const uint4*)(Bg0 + (st + 1) * 32);
            pb1 = *(const uint4*)(Bg1 + (st + 1) * 32);
        }

        #pragma unroll
        for (int ks = 0; ks < 2; ks++) {
            const int kc = ks * 16 + lr * 2;
            uint32_t af[4][4];
            #pragma unroll
            for (int i = 0; i < 4; i++) {
                const __nv_bfloat16* base = &sA[buf][(wm * 64 + i * 16 + lq) * SROW + kc];
                af[i][0] = *(const uint32_t*)(base);
                af[i][1] = *(const uint32_t*)(base + 8 * SROW);
                af[i][2] = *(const uint32_t*)(base + 8);
                af[i][3] = *(const uint32_t*)(base + 8 * SROW + 8);
            }
            uint32_t bfr[4][2];
            #pragma unroll
            for (int j = 0; j < 4; j++) {
                const __nv_bfloat16* base = &sB[buf][(wn * 32 + j * 8 + lq) * SROW + kc];
                bfr[j][0] = *(const uint32_t*)(base);
                bfr[j][1] = *(const uint32_t*)(base + 8);
            }
            #pragma unroll
            for (int i = 0; i < 4; i++)
                #pragma unroll
                for (int j = 0; j < 4; j++)
                    mma16816(acc[i][j], af[i], bfr[j]);
        }

        if (st + 1 < NSTAGE) {
            int nb = buf ^ 1;
            *(uint4*)&sA[nb][sa0] = pa0; *(uint4*)&sA[nb][sa1] = pa1;
            *(uint4*)&sB[nb][sa0] = pb0; *(uint4*)&sB[nb][sa1] = pb1;
            __syncthreads();
            buf = nb;
        }
    }

    // epilogue: c0,c1 at (row, col..col+1); c2,c3 at (row+8, ...)
    float* Cp = Cpart + (size_t)s * (B_SZ * F_SZ);
    #pragma unroll
    for (int i = 0; i < 4; i++) {
        #pragma unroll
        for (int j = 0; j < 4; j++) {
            int row = bm + wm * 64 + i * 16 + lq;
            int col = bn + wn * 32 + j * 8 + lr * 2;
            *(float2*)(Cp + (size_t)row * F_SZ + col) =
                make_float2(acc[i][j][0], acc[i][j][1]);
            *(float2*)(Cp + (size_t)(row + 8) * F_SZ + col) =
                make_float2(acc[i][j][2], acc[i][j][3]);
        }
    }
}

// ---------------------------------------------------------------------------
// Reduce SPLITK partials (+ bias) -> fp32 out. 4 float4/thread, grid 128.
// ---------------------------------------------------------------------------
__global__ __launch_bounds__(256) void reduce_k(const float* __restrict__ part,
                                                const float* __restrict__ bias,
                                                float* __restrict__ out)
{
    const int base = blockIdx.x * 1024 + threadIdx.x;
    const int Q = B_SZ * F_SZ / 4;
    const float4* p = (const float4*)part;
    float4 a[4], b[4], c[4], d[4];
    #pragma unroll
    for (int u = 0; u < 4; u++) {
        int idx = base + u * 256;
        a[u] = p[idx]; b[u] = p[idx + Q]; c[u] = p[idx + 2 * Q]; d[u] = p[idx + 3 * Q];
    }
    #pragma unroll
    for (int u = 0; u < 4; u++) {
        int idx = base + u * 256;
        float4 bb = ((const float4*)bias)[idx & 255];
        float4 o;
        o.x = (a[u].x + b[u].x) + (c[u].x + d[u].x) + bb.x;
        o.y = (a[u].y + b[u].y) + (c[u].y + d[u].y) + bb.y;
        o.z = (a[u].z + b[u].z) + (c[u].z + d[u].z) + bb.z;
        o.w = (a[u].w + b[u].w) + (c[u].w + d[u].w) + bb.w;
        ((float4*)out)[idx] = o;
    }
}

// ---------------------------------------------------------------------------
// Attention partial (UNCHANGED: 92us, 78% DRAM). grid (B, TSPLIT).
// ---------------------------------------------------------------------------
__global__ __launch_bounds__(256, 2) void attn_part(const float* __restrict__ x,
                                                    const float* __restrict__ qkpart,
                                                    float* __restrict__ pacc,
                                                    float2* __restrict__ pmz)
{
    const int b = blockIdx.x;
    const int h = blockIdx.y;
    const int tid = threadIdx.x;
    const int w = tid >> 5;
    const int l = tid & 31;

    __shared__ float red[8][256];
    __shared__ float s_tile[8];

    float4 qk;
    {
        const int Q = B_SZ * F_SZ / 4;
        const int idx = b * 256 + tid;
        const float4* p = (const float4*)qkpart;
        float4 a = p[idx], bb = p[idx + Q], c = p[idx + 2 * Q], d = p[idx + 3 * Q];
        qk = make_float4((a.x + bb.x) + (c.x + d.x),
                         (a.y + bb.y) + (c.y + d.y),
                         (a.z + bb.z) + (c.z + d.z),
                         (a.w + bb.w) + (c.w + d.w));
    }

    const float4* x4 = (const float4*)(x + (size_t)b * T_SZ * F_SZ
                                         + (size_t)h * TCH * F_SZ);
    float4 cur[8], nxt[8];
    #pragma unroll
    for (int i = 0; i < 8; i++) cur[i] = x4[(size_t)i * 256 + tid];

    float m = -INFINITY, Z = 0.0f;
    float4 acc = make_float4(0.f, 0.f, 0.f, 0.f);

    #pragma unroll
    for (int it = 0; it < NIT; it++) {
        if (it + 1 < NIT) {
            #pragma unroll
            for (int i = 0; i < 8; i++)
                nxt[i] = x4[(size_t)((it + 1) * 8 + i) * 256 + tid];
        }
        #pragma unroll
        for (int i = 0; i < 8; i++) {
            float4 xv = cur[i];
            red[i][tid] = xv.x * qk.x + xv.y * qk.y + xv.z * qk.z + xv.w * qk.w;
        }
        __syncthreads();
        {
            float s = 0.f;
            #pragma unroll
            for (int j = 0; j < 8; j++) s += red[w][l + 32 * j];
            #pragma unroll
            for (int off = 16; off; off >>= 1)
                s += __shfl_down_sync(0xffffffffu, s, off);
            if (l == 0) s_tile[w] = s;
        }
        __syncthreads();

        float tm = s_tile[0];
        #pragma unroll
        for (int t = 1; t < 8; t++) tm = fmaxf(tm, s_tile[t]);
        float m_new = fmaxf(m, tm);
        float scale = __expf(m - m_new);
        Z *= scale;
        acc.x *= scale; acc.y *= scale; acc.z *= scale; acc.w *= scale;
        #pragma unroll
        for (int t = 0; t < 8; t++) {
            float wt = __expf(s_tile[t] - m_new);
            Z += wt;
            float4 xv = cur[t];
            acc.x += wt * xv.x; acc.y += wt * xv.y;
            acc.z += wt * xv.z; acc.w += wt * xv.w;
        }
        m = m_new;
        if (it + 1 < NIT) {
            #pragma unroll
            for (int i = 0; i < 8; i++) cur[i] = nxt[i];
        }
    }

    ((float4*)pacc)[(size_t)(b * TSPLIT + h) * 256 + tid] = acc;
    if (tid == 0) pmz[b * TSPLIT + h] = make_float2(m, Z);
}

// ---------------------------------------------------------------------------
// Combine T-chunks, normalize, convert to bf16 A-pattern triple for GEMM3.
// ---------------------------------------------------------------------------
__global__ __launch_bounds__(256) void attn_combine_conv(const float* __restrict__ pacc,
                                                         const float2* __restrict__ pmz,
                                                         __nv_bfloat16* __restrict__ out)
{
    const int b = blockIdx.x;
    const int tid = threadIdx.x;

    float2 mz[TSPLIT];
    #pragma unroll
    for (int i = 0; i < TSPLIT; i++) mz[i] = pmz[TSPLIT * b + i];
    float m = mz[0].x;
    #pragma unroll
    for (int i = 1; i < TSPLIT; i++) m = fmaxf(m, mz[i].x);
    float sc[TSPLIT], Z = 0.f;
    #pragma unroll
    for (int i = 0; i < TSPLIT; i++) { sc[i] = __expf(mz[i].x - m); Z += mz[i].y * sc[i]; }
    float inv = 1.0f / Z;

    float4 o = make_float4(0.f, 0.f, 0.f, 0.f);
    #pragma unroll
    for (int i = 0; i < TSPLIT; i++) {
        float4 a = ((const float4*)pacc)[(size_t)(TSPLIT * b + i) * 256 + tid];
        o.x += a.x * sc[i]; o.y += a.y * sc[i];
        o.z += a.z * sc[i]; o.w += a.w * sc[i];
    }
    o.x *= inv; o.y *= inv; o.z *= inv; o.w *= inv;

    uint2 hi, lo; split4(o, hi, lo);
    __nv_bfloat16* base = out + (size_t)b * KP + tid * 4;
    *(uint2*)(base)        = hi;
    *(uint2*)(base + 1024) = lo;
    *(uint2*)(base + 2048) = hi;
}

// ---------------------------------------------------------------------------
extern "C" void kernel_launch(void* const* d_in, const int* in_sizes, int n_in,
                              void* d_out, int out_size)
{
    const float* z  = (const float*)d_in[0];   // [B,F]
    const float* x  = (const float*)d_in[1];   // [B,T,F]
    const float* Wq = (const float*)d_in[2];   // [D,F]
    const float* Wk = (const float*)d_in[3];   // [D,F]
    const float* Wv = (const float*)d_in[4];   // [D,F]
    const float* bq = (const float*)d_in[5];   // [D]
    // d_in[6] = bk: softmax-invariant -> dropped
    const float* bv = (const float*)d_in[7];   // [D]
    float* out = (float*)d_out;                // [B,D]

    float *part, *pacc;
    float2* pmz;
    __nv_bfloat16 *actA, *WqB, *WkB, *WvB;
    cudaGetSymbolAddress((void**)&part, g_part);
    cudaGetSymbolAddress((void**)&pacc, g_pacc);
    cudaGetSymbolAddress((void**)&pmz,  g_pmz);
    cudaGetSymbolAddress((void**)&actA, g_actA);
    cudaGetSymbolAddress((void**)&WqB,  g_WqB);
    cudaGetSymbolAddress((void**)&WkB,  g_WkB);
    cudaGetSymbolAddress((void**)&WvB,  g_WvB);

    dim3 mgrid(8, 4, SPLITK);   // 128 CTAs per GEMM

    // conversions (independent of each other)
    conv_w_nt<<<1024, 256>>>(Wq, WqB);
    conv_w_t<<<dim3(32, 32), dim3(32, 8)>>>(Wk, WkB);
    conv_w_nt<<<1024, 256>>>(Wv, WvB);
    conv_act<<<512, 256>>>(z, actA);

    // 1. q = z @ Wq^T + bq  (bf16-split tensor GEMM + reduce/convert)
    mma_gemm<<<mgrid, 256>>>(actA, WqB, part);
    reduce_conv<<<512, 256>>>(part, bq, actA);
    // 2. qk = q @ Wk  (partials consumed directly by attn_part)
    mma_gemm<<<mgrid, 256>>>(actA, WkB, part);
    // 3. fused scores + softmax + weighted-input accumulation
    attn_part<<<dim3(B_SZ, TSPLIT), 256>>>(x, part, pacc, pmz);
    attn_combine_conv<<<B_SZ, 256>>>(pacc, pmz, actA);
    // 4. out = ctxf @ Wv^T + bv
    mma_gemm<<<mgrid, 256>>>(actA, WvB, part);
    reduce_k<<<128, 256>>>(part, bv, out);
}